// round 5
// baseline (speedup 1.0000x reference)
#include <cuda_runtime.h>

typedef unsigned long long ull;

#define B_TOTAL  4096
#define T_STEPS  512
#define H        64
#define NB       32      // batch per CTA
#define NTHREADS 128     // 4 batch-groups (warps) x 32 gate-pair lanes
#define BT       8       // batches per thread

// shared memory layout in ull (8B) units:
//   w0t  [64][128]  : {W_hh0[2p][k], W_hh0[2p+1][k]}              64 KB
//   wct  [128][128] : k<64 -> W_ih1, k>=64 -> W_hh1 (transposed) 128 KB
//   hcat [32][128]  : dup-pairs {h,h}; [0:64)=layer0 h, [64:128)=layer1 h  32 KB
#define W0T_OFF   0
#define WCT_OFF   8192
#define HCAT_OFF  24576
#define SMEM_ULLS (24576 + 4096)
#define SMEM_BYTES (SMEM_ULLS * 8)   // 229376 < 232448 max

__device__ __forceinline__ ull pack2(float a, float b){
    ull r; asm("mov.b64 %0, {%1, %2};" : "=l"(r) : "f"(a), "f"(b)); return r;
}
__device__ __forceinline__ ull dup2(float a){
    ull r; asm("mov.b64 %0, {%1, %1};" : "=l"(r) : "f"(a)); return r;
}
__device__ __forceinline__ void fma2(ull &d, ull a, ull b){
    asm("fma.rn.f32x2 %0, %1, %2, %0;" : "+l"(d) : "l"(a), "l"(b));
}
__device__ __forceinline__ float2 unpack2(ull v){
    float lo, hi; asm("mov.b64 {%0, %1}, %2;" : "=f"(lo), "=f"(hi) : "l"(v));
    return make_float2(lo, hi);
}
__device__ __forceinline__ float sigm(float x){
    float e = __expf(-fabsf(x));
    float s = __fdividef(1.0f, 1.0f + e);
    return (x >= 0.0f) ? s : 1.0f - s;
}
__device__ __forceinline__ float tanh_f(float x){
    float e = __expf(-2.0f * fabsf(x));
    float t = __fdividef(1.0f - e, 1.0f + e);
    return copysignf(t, x);
}

extern __shared__ ull smem[];

__global__ void __launch_bounds__(NTHREADS, 1)
lstm_forecaster_kernel(const float* __restrict__ x,
                       const float* __restrict__ W_ih0, const float* __restrict__ W_hh0,
                       const float* __restrict__ b_ih0, const float* __restrict__ b_hh0,
                       const float* __restrict__ W_ih1, const float* __restrict__ W_hh1,
                       const float* __restrict__ b_ih1, const float* __restrict__ b_hh1,
                       const float* __restrict__ W_fc,  const float* __restrict__ b_fc,
                       float* __restrict__ out)
{
    ull* w0t  = smem + W0T_OFF;
    ull* wct  = smem + WCT_OFF;
    ull* hcat = smem + HCAT_OFF;

    const int tid   = threadIdx.x;
    const int hp    = tid & 31;        // gate-pair lane (h channels 2hp, 2hp+1)
    const int bg    = tid >> 5;        // warp = batch group
    const int bloc0 = bg * BT;         // local batch base for this thread
    const int gb0   = blockIdx.x * NB; // global batch base for this CTA

    // ---- build transposed, pair-packed weight tiles in smem ----
    for (int i = tid; i < 64 * 128; i += NTHREADS){
        int k = i >> 7, p = i & 127;
        w0t[i] = pack2(W_hh0[(2*p)*H + k], W_hh0[(2*p+1)*H + k]);
    }
    for (int i = tid; i < 128 * 128; i += NTHREADS){
        int k = i >> 7, p = i & 127;
        const float* Wsrc = (k < H) ? W_ih1 : W_hh1;
        int kk = k & (H - 1);
        wct[i] = pack2(Wsrc[(2*p)*H + kk], Wsrc[(2*p+1)*H + kk]);
    }
    for (int i = tid; i < NB * 128; i += NTHREADS) hcat[i] = 0ull;

    // ---- per-thread gate-pair constants (registers, not smem) ----
    ull bias0[4], bias1[4], wih0p[4];
    #pragma unroll
    for (int q = 0; q < 4; q++){
        int p = hp + 32*q;
        int g0 = 2*p, g1 = 2*p + 1;
        bias0[q] = pack2(b_ih0[g0] + b_hh0[g0], b_ih0[g1] + b_hh0[g1]);
        bias1[q] = pack2(b_ih1[g0] + b_hh1[g0], b_ih1[g1] + b_hh1[g1]);
        wih0p[q] = pack2(W_ih0[g0], W_ih0[g1]);
    }

    float c0[BT][2], c1[BT][2];
    #pragma unroll
    for (int j = 0; j < BT; j++){
        c0[j][0] = c0[j][1] = 0.0f;
        c1[j][0] = c1[j][1] = 0.0f;
    }

    __syncthreads();

    for (int t = 0; t < T_STEPS; t++){
        // x inputs for this step (global loads issued early, consumed after GEMM0)
        float xv[BT];
        #pragma unroll
        for (int j = 0; j < BT; j++)
            xv[j] = __ldg(&x[(gb0 + bloc0 + j) * T_STEPS + t]);

        ull acc[BT][4];

        // ======== layer 0: gates = bias + x*W_ih0 + h0_prev @ W_hh0^T ========
        #pragma unroll
        for (int j = 0; j < BT; j++){
            #pragma unroll
            for (int q = 0; q < 4; q++) acc[j][q] = bias0[q];
        }

        #pragma unroll 2
        for (int k = 0; k < H; k += 2){
            const ull* wr = &w0t[k * 128];
            ull wA0 = wr[hp],       wA1 = wr[hp + 32],     wA2 = wr[hp + 64],     wA3 = wr[hp + 96];
            ull wB0 = wr[128 + hp], wB1 = wr[128 + hp+32], wB2 = wr[128 + hp+64], wB3 = wr[128 + hp+96];
            #pragma unroll
            for (int j = 0; j < BT; j++){
                ulonglong2 hv = *reinterpret_cast<const ulonglong2*>(&hcat[(bloc0 + j) * 128 + k]);
                fma2(acc[j][0], hv.x, wA0); fma2(acc[j][1], hv.x, wA1);
                fma2(acc[j][2], hv.x, wA2); fma2(acc[j][3], hv.x, wA3);
                fma2(acc[j][0], hv.y, wB0); fma2(acc[j][1], hv.y, wB1);
                fma2(acc[j][2], hv.y, wB2); fma2(acc[j][3], hv.y, wB3);
            }
        }
        #pragma unroll
        for (int j = 0; j < BT; j++){
            ull xd = dup2(xv[j]);
            #pragma unroll
            for (int q = 0; q < 4; q++) fma2(acc[j][q], xd, wih0p[q]);
        }
        __syncthreads();   // all lanes done reading hcat[*][0:64)

        // ---- layer 0 cell update (fully thread-local; c0 in regs) ----
        #pragma unroll
        for (int j = 0; j < BT; j++){
            float2 gi = unpack2(acc[j][0]);
            float2 gf = unpack2(acc[j][1]);
            float2 gg = unpack2(acc[j][2]);
            float2 go = unpack2(acc[j][3]);
            float ccx = sigm(gf.x) * c0[j][0] + sigm(gi.x) * tanh_f(gg.x);
            float ccy = sigm(gf.y) * c0[j][1] + sigm(gi.y) * tanh_f(gg.y);
            c0[j][0] = ccx; c0[j][1] = ccy;
            float hx = sigm(go.x) * tanh_f(ccx);
            float hy = sigm(go.y) * tanh_f(ccy);
            ulonglong2 st; st.x = dup2(hx); st.y = dup2(hy);
            *reinterpret_cast<ulonglong2*>(&hcat[(bloc0 + j) * 128 + 2*hp]) = st;
        }
        __syncthreads();   // new layer-0 h visible

        // ======== layer 1: gates = bias + [h0_t ; h1_prev] @ [W_ih1;W_hh1]^T ========
        #pragma unroll
        for (int j = 0; j < BT; j++){
            #pragma unroll
            for (int q = 0; q < 4; q++) acc[j][q] = bias1[q];
        }

        #pragma unroll 2
        for (int k = 0; k < 2*H; k += 2){
            const ull* wr = &wct[k * 128];
            ull wA0 = wr[hp],       wA1 = wr[hp + 32],     wA2 = wr[hp + 64],     wA3 = wr[hp + 96];
            ull wB0 = wr[128 + hp], wB1 = wr[128 + hp+32], wB2 = wr[128 + hp+64], wB3 = wr[128 + hp+96];
            #pragma unroll
            for (int j = 0; j < BT; j++){
                ulonglong2 hv = *reinterpret_cast<const ulonglong2*>(&hcat[(bloc0 + j) * 128 + k]);
                fma2(acc[j][0], hv.x, wA0); fma2(acc[j][1], hv.x, wA1);
                fma2(acc[j][2], hv.x, wA2); fma2(acc[j][3], hv.x, wA3);
                fma2(acc[j][0], hv.y, wB0); fma2(acc[j][1], hv.y, wB1);
                fma2(acc[j][2], hv.y, wB2); fma2(acc[j][3], hv.y, wB3);
            }
        }
        __syncthreads();   // all lanes done reading hcat[*][64:128)

        // ---- layer 1 cell update ----
        #pragma unroll
        for (int j = 0; j < BT; j++){
            float2 gi = unpack2(acc[j][0]);
            float2 gf = unpack2(acc[j][1]);
            float2 gg = unpack2(acc[j][2]);
            float2 go = unpack2(acc[j][3]);
            float ccx = sigm(gf.x) * c1[j][0] + sigm(gi.x) * tanh_f(gg.x);
            float ccy = sigm(gf.y) * c1[j][1] + sigm(gi.y) * tanh_f(gg.y);
            c1[j][0] = ccx; c1[j][1] = ccy;
            float hx = sigm(go.x) * tanh_f(ccx);
            float hy = sigm(go.y) * tanh_f(ccy);
            ulonglong2 st; st.x = dup2(hx); st.y = dup2(hy);
            *reinterpret_cast<ulonglong2*>(&hcat[(bloc0 + j) * 128 + H + 2*hp]) = st;
        }
        __syncthreads();   // new layer-1 h visible for next step
    }

    // ---- final FC: out[b] = h1_last . W_fc + b_fc ----
    if (tid < NB){
        const float2* hrow = reinterpret_cast<const float2*>(&hcat[tid * 128 + H]);
        float s = b_fc[0];
        #pragma unroll
        for (int h = 0; h < H; h++)
            s += hrow[h].x * W_fc[h];
        out[gb0 + tid] = s;
    }
}

extern "C" void kernel_launch(void* const* d_in, const int* in_sizes, int n_in,
                              void* d_out, int out_size)
{
    const float* x     = (const float*)d_in[0];
    const float* W_ih0 = (const float*)d_in[1];
    const float* W_hh0 = (const float*)d_in[2];
    const float* b_ih0 = (const float*)d_in[3];
    const float* b_hh0 = (const float*)d_in[4];
    const float* W_ih1 = (const float*)d_in[5];
    const float* W_hh1 = (const float*)d_in[6];
    const float* b_ih1 = (const float*)d_in[7];
    const float* b_hh1 = (const float*)d_in[8];
    const float* W_fc  = (const float*)d_in[9];
    const float* b_fc  = (const float*)d_in[10];
    float* out = (float*)d_out;

    cudaFuncSetAttribute(lstm_forecaster_kernel,
                         cudaFuncAttributeMaxDynamicSharedMemorySize, SMEM_BYTES);
    lstm_forecaster_kernel<<<B_TOTAL / NB, NTHREADS, SMEM_BYTES>>>(
        x, W_ih0, W_hh0, b_ih0, b_hh0,
        W_ih1, W_hh1, b_ih1, b_hh1, W_fc, b_fc, out);
}

// round 6
// speedup vs baseline: 1.1429x; 1.1429x over previous
#include <cuda_runtime.h>

typedef unsigned long long ull;

#define B_TOTAL  4096
#define T_STEPS  512
#define H        64
#define NB       32      // batches per CTA
#define NTHREADS 256     // warps 0-3: layer0 ("A"), warps 4-7: layer1 ("B")
#define BT       8       // batches per thread (both groups)

// shared memory layout (bytes):
//   w0t  [64][128]  ull : {W_hh0[2p][k], W_hh0[2p+1][k]}          @ 0       (65536)
//   wct  [128][128] ull : k<64 -> W_ih1, k>=64 -> W_hh1 pairs     @ 65536   (131072)
//   h0   [2][32][64] float : double-buffered layer-0 h (plain)    @ 196608  (16384)
//   h1   [32][64]    float : layer-1 h (plain)                    @ 212992  (8192)
#define W0T_ULL_OFF 0
#define WCT_ULL_OFF 8192
#define H0_BYTE_OFF 196608
#define H1_BYTE_OFF 212992
#define SMEM_BYTES  221184   // <= 232448 max dynamic smem

__device__ __forceinline__ ull pack2(float a, float b){
    ull r; asm("mov.b64 %0, {%1, %2};" : "=l"(r) : "f"(a), "f"(b)); return r;
}
__device__ __forceinline__ ull dup2(float a){
    ull r; asm("mov.b64 %0, {%1, %1};" : "=l"(r) : "f"(a)); return r;
}
__device__ __forceinline__ void fma2(ull &d, ull a, ull b){
    asm("fma.rn.f32x2 %0, %1, %2, %0;" : "+l"(d) : "l"(a), "l"(b));
}
__device__ __forceinline__ float2 unpack2(ull v){
    float lo, hi; asm("mov.b64 {%0, %1}, %2;" : "=f"(lo), "=f"(hi) : "l"(v));
    return make_float2(lo, hi);
}
__device__ __forceinline__ float sigm(float x){
    float e = __expf(-fabsf(x));
    float s = __fdividef(1.0f, 1.0f + e);
    return (x >= 0.0f) ? s : 1.0f - s;
}
__device__ __forceinline__ float tanh_f(float x){
    float e = __expf(-2.0f * fabsf(x));
    float t = __fdividef(1.0f - e, 1.0f + e);
    return copysignf(t, x);
}

extern __shared__ ull smem[];

// GEMM over one 64-deep K block: acc[j][q] += h[j][k] * Wpair[k][q-lane]
__device__ __forceinline__ void gemm64(ull acc[BT][4], const ull* __restrict__ wt,
                                       const float* __restrict__ hrow, int hp)
{
    #pragma unroll 2
    for (int k = 0; k < H; k += 2){
        const ull* wr = wt + k * 128;
        ull wA0 = wr[hp],       wA1 = wr[hp + 32],     wA2 = wr[hp + 64],     wA3 = wr[hp + 96];
        ull wB0 = wr[128 + hp], wB1 = wr[128 + hp+32], wB2 = wr[128 + hp+64], wB3 = wr[128 + hp+96];
        #pragma unroll
        for (int j = 0; j < BT; j++){
            float2 hv = *reinterpret_cast<const float2*>(&hrow[j * H + k]);
            ull hx = dup2(hv.x);
            ull hy = dup2(hv.y);
            fma2(acc[j][0], hx, wA0); fma2(acc[j][1], hx, wA1);
            fma2(acc[j][2], hx, wA2); fma2(acc[j][3], hx, wA3);
            fma2(acc[j][0], hy, wB0); fma2(acc[j][1], hy, wB1);
            fma2(acc[j][2], hy, wB2); fma2(acc[j][3], hy, wB3);
        }
    }
}

// LSTM cell update for BT batches; writes plain-float h pairs into hw
__device__ __forceinline__ void cell_update(ull acc[BT][4], float c[BT][2],
                                            float* __restrict__ hw, int hp)
{
    #pragma unroll
    for (int j = 0; j < BT; j++){
        float2 gi = unpack2(acc[j][0]);
        float2 gf = unpack2(acc[j][1]);
        float2 gg = unpack2(acc[j][2]);
        float2 go = unpack2(acc[j][3]);
        float ccx = sigm(gf.x) * c[j][0] + sigm(gi.x) * tanh_f(gg.x);
        float ccy = sigm(gf.y) * c[j][1] + sigm(gi.y) * tanh_f(gg.y);
        c[j][0] = ccx; c[j][1] = ccy;
        float hx = sigm(go.x) * tanh_f(ccx);
        float hy = sigm(go.y) * tanh_f(ccy);
        *reinterpret_cast<float2*>(&hw[j * H + 2 * hp]) = make_float2(hx, hy);
    }
}

__global__ void __launch_bounds__(NTHREADS, 1)
lstm_forecaster_kernel(const float* __restrict__ x,
                       const float* __restrict__ W_ih0, const float* __restrict__ W_hh0,
                       const float* __restrict__ b_ih0, const float* __restrict__ b_hh0,
                       const float* __restrict__ W_ih1, const float* __restrict__ W_hh1,
                       const float* __restrict__ b_ih1, const float* __restrict__ b_hh1,
                       const float* __restrict__ W_fc,  const float* __restrict__ b_fc,
                       float* __restrict__ out)
{
    ull*   w0t = smem + W0T_ULL_OFF;
    ull*   wct = smem + WCT_ULL_OFF;
    float* h0  = reinterpret_cast<float*>(reinterpret_cast<char*>(smem) + H0_BYTE_OFF);
    float* h1  = reinterpret_cast<float*>(reinterpret_cast<char*>(smem) + H1_BYTE_OFF);

    const int tid   = threadIdx.x;
    const int hp    = tid & 31;          // gate-pair lane (gate channels 2hp.. within each group of 64)
    const int wid   = tid >> 5;
    const bool isA  = (wid < 4);         // layer-0 group
    const int bg    = wid & 3;           // batch group within the layer group
    const int bloc0 = bg * BT;
    const int gb0   = blockIdx.x * NB;

    // ---- build transposed, pair-packed weight tiles ----
    for (int i = tid; i < 64 * 128; i += NTHREADS){
        int k = i >> 7, p = i & 127;
        w0t[i] = pack2(W_hh0[(2*p)*H + k], W_hh0[(2*p+1)*H + k]);
    }
    for (int i = tid; i < 128 * 128; i += NTHREADS){
        int k = i >> 7, p = i & 127;
        const float* Wsrc = (k < H) ? W_ih1 : W_hh1;
        int kk = k & (H - 1);
        wct[i] = pack2(Wsrc[(2*p)*H + kk], Wsrc[(2*p+1)*H + kk]);
    }
    for (int i = tid; i < 2 * NB * H; i += NTHREADS) h0[i] = 0.0f;
    for (int i = tid; i < NB * H;     i += NTHREADS) h1[i] = 0.0f;

    // ---- per-group gate-pair constants in registers ----
    ull bias[4], wih0p[4];
    #pragma unroll
    for (int q = 0; q < 4; q++){
        int p = hp + 32*q;
        int g0 = 2*p, g1 = 2*p + 1;
        if (isA){
            bias[q]  = pack2(b_ih0[g0] + b_hh0[g0], b_ih0[g1] + b_hh0[g1]);
            wih0p[q] = pack2(W_ih0[g0], W_ih0[g1]);
        } else {
            bias[q]  = pack2(b_ih1[g0] + b_hh1[g0], b_ih1[g1] + b_hh1[g1]);
            wih0p[q] = 0ull;
        }
    }

    float cst[BT][2];
    #pragma unroll
    for (int j = 0; j < BT; j++){ cst[j][0] = 0.0f; cst[j][1] = 0.0f; }

    __syncthreads();

    // Software pipeline: iteration i -> group A computes layer-0 step i,
    // group B computes layer-1 step i-1. One barrier per iteration.
    for (int i = 0; i <= T_STEPS; i++){
        const float* h0_rd = h0 + ((i + 1) & 1) * (NB * H);  // h0[i-1]
        float*       h0_wr = h0 + (i & 1)       * (NB * H);  // h0[i]

        if (isA){
            if (i < T_STEPS){
                float xv[BT];
                #pragma unroll
                for (int j = 0; j < BT; j++)
                    xv[j] = __ldg(&x[(gb0 + bloc0 + j) * T_STEPS + i]);

                ull acc[BT][4];
                #pragma unroll
                for (int j = 0; j < BT; j++){
                    #pragma unroll
                    for (int q = 0; q < 4; q++) acc[j][q] = bias[q];
                }

                gemm64(acc, w0t, h0_rd + bloc0 * H, hp);

                #pragma unroll
                for (int j = 0; j < BT; j++){
                    ull xd = dup2(xv[j]);
                    #pragma unroll
                    for (int q = 0; q < 4; q++) fma2(acc[j][q], xd, wih0p[q]);
                }

                // A's own GEMM is done; h0_wr is the buffer nobody reads this
                // iteration -> update immediately, no intra-step barrier.
                cell_update(acc, cst, h0_wr + bloc0 * H, hp);
            }
        } else {
            if (i > 0){
                ull acc[BT][4];
                #pragma unroll
                for (int j = 0; j < BT; j++){
                    #pragma unroll
                    for (int q = 0; q < 4; q++) acc[j][q] = bias[q];
                }

                gemm64(acc, wct,            h0_rd + bloc0 * H, hp);  // W_ih1 * h0[i-1]
                gemm64(acc, wct + 64 * 128, h1    + bloc0 * H, hp);  // W_hh1 * h1[i-2]

                // B reads only its own batches' h1 rows in the GEMM above and
                // overwrites the same rows here -> warp-local, safe.
                cell_update(acc, cst, h1 + bloc0 * H, hp);
            }
        }

        // Publishes A's h0[i] for next iteration's readers, and guarantees all
        // readers of h0[i-1] finished before A overwrites that buffer at i+1.
        // Also orders B's h1 write before next iteration's h1 reads.
        __syncthreads();
    }

    // ---- final FC on h1[T-1] ----
    if (tid < NB){
        const float* hrow = &h1[tid * H];
        float s = b_fc[0];
        #pragma unroll
        for (int h = 0; h < H; h++)
            s += hrow[h] * W_fc[h];
        out[gb0 + tid] = s;
    }
}

extern "C" void kernel_launch(void* const* d_in, const int* in_sizes, int n_in,
                              void* d_out, int out_size)
{
    const float* x     = (const float*)d_in[0];
    const float* W_ih0 = (const float*)d_in[1];
    const float* W_hh0 = (const float*)d_in[2];
    const float* b_ih0 = (const float*)d_in[3];
    const float* b_hh0 = (const float*)d_in[4];
    const float* W_ih1 = (const float*)d_in[5];
    const float* W_hh1 = (const float*)d_in[6];
    const float* b_ih1 = (const float*)d_in[7];
    const float* b_hh1 = (const float*)d_in[8];
    const float* W_fc  = (const float*)d_in[9];
    const float* b_fc  = (const float*)d_in[10];
    float* out = (float*)d_out;

    cudaFuncSetAttribute(lstm_forecaster_kernel,
                         cudaFuncAttributeMaxDynamicSharedMemorySize, SMEM_BYTES);
    lstm_forecaster_kernel<<<B_TOTAL / NB, NTHREADS, SMEM_BYTES>>>(
        x, W_ih0, W_hh0, b_ih0, b_hh0,
        W_ih1, W_hh1, b_ih1, b_hh1, W_fc, b_fc, out);
}

// round 9
// speedup vs baseline: 1.2530x; 1.0963x over previous
#include <cuda_runtime.h>

typedef unsigned long long ull;

#define B_TOTAL  4096
#define T_STEPS  512
#define H        64
#define NWARPS   8
#define NTHREADS 256
#define J        4            // batches per warp (warp owns them through BOTH layers)
#define NB       (NWARPS*J)   // 32 batches per CTA

// smem layout in ull units:
//   w0 [32][256] : w0[kp][row] = {W_hh0[row][2kp], W_hh0[row][2kp+1]}          64 KB
//   wc [64][256] : kp<32 -> W_ih1 pairs, kp>=32 -> W_hh1 pairs                128 KB
//   hb : per-warp private: h0[J][32] ull + h1[J][32] ull (k-packed h pairs)    16 KB
#define W0_ULL   0
#define WC_ULL   (32*256)
#define HB_ULL   (WC_ULL + 64*256)
#define SMEM_ULLS (HB_ULL + NWARPS * 2 * J * 32)
#define SMEM_BYTES (SMEM_ULLS * 8)   // 212992 <= 232448

__device__ __forceinline__ ull pack2(float a, float b){
    ull r; asm("mov.b64 %0, {%1, %2};" : "=l"(r) : "f"(a), "f"(b)); return r;
}
__device__ __forceinline__ void fma2(ull &d, ull a, ull b){
    asm("fma.rn.f32x2 %0, %1, %2, %0;" : "+l"(d) : "l"(a), "l"(b));
}
__device__ __forceinline__ float2 unpack2(ull v){
    float lo, hi; asm("mov.b64 {%0, %1}, %2;" : "=f"(lo), "=f"(hi) : "l"(v));
    return make_float2(lo, hi);
}
__device__ __forceinline__ float sum2(ull v){
    float2 p = unpack2(v); return p.x + p.y;
}
__device__ __forceinline__ float sigm(float x){
    float e = __expf(-fabsf(x));
    float s = __fdividef(1.0f, 1.0f + e);
    return (x >= 0.0f) ? s : 1.0f - s;
}
__device__ __forceinline__ float tanh_f(float x){
    float e = __expf(-2.0f * fabsf(x));
    float t = __fdividef(1.0f - e, 1.0f + e);
    return copysignf(t, x);
}

extern __shared__ ull smem[];

// acc[j][g][ch] += over a 64-deep K block; k-packed: each FFMA2 does k and k+1
// for one gate row. hb[j*32+kp] = {h_2kp, h_2kp+1}. w[kp*256 + row] = weight pair.
__device__ __forceinline__ void gemm64k(ull acc[J][4][2], const ull* w,
                                        const ull* hb, int hp)
{
    #pragma unroll 4
    for (int kq = 0; kq < 16; kq++){
        const int kp0 = 2 * kq;
        const ull* wr0 = w + kp0 * 256 + 2 * hp;   // rows {2hp, 2hp+1}, k-pair kp0
        const ull* wr1 = wr0 + 256;                // k-pair kp0+1
        ulonglong2 wi0 = *(const ulonglong2*)(wr0 +   0);
        ulonglong2 wf0 = *(const ulonglong2*)(wr0 +  64);
        ulonglong2 wg0 = *(const ulonglong2*)(wr0 + 128);
        ulonglong2 wo0 = *(const ulonglong2*)(wr0 + 192);
        ulonglong2 wi1 = *(const ulonglong2*)(wr1 +   0);
        ulonglong2 wf1 = *(const ulonglong2*)(wr1 +  64);
        ulonglong2 wg1 = *(const ulonglong2*)(wr1 + 128);
        ulonglong2 wo1 = *(const ulonglong2*)(wr1 + 192);
        #pragma unroll
        for (int j = 0; j < J; j++){
            ulonglong2 hv = *(const ulonglong2*)(hb + j * 32 + kp0);  // broadcast
            fma2(acc[j][0][0], hv.x, wi0.x); fma2(acc[j][0][1], hv.x, wi0.y);
            fma2(acc[j][1][0], hv.x, wf0.x); fma2(acc[j][1][1], hv.x, wf0.y);
            fma2(acc[j][2][0], hv.x, wg0.x); fma2(acc[j][2][1], hv.x, wg0.y);
            fma2(acc[j][3][0], hv.x, wo0.x); fma2(acc[j][3][1], hv.x, wo0.y);
            fma2(acc[j][0][0], hv.y, wi1.x); fma2(acc[j][0][1], hv.y, wi1.y);
            fma2(acc[j][1][0], hv.y, wf1.x); fma2(acc[j][1][1], hv.y, wf1.y);
            fma2(acc[j][2][0], hv.y, wg1.x); fma2(acc[j][2][1], hv.y, wg1.y);
            fma2(acc[j][3][0], hv.y, wo1.x); fma2(acc[j][3][1], hv.y, wo1.y);
        }
    }
}

__global__ void __launch_bounds__(NTHREADS, 1)
lstm_forecaster_kernel(const float* __restrict__ x,
                       const float* __restrict__ W_ih0, const float* __restrict__ W_hh0,
                       const float* __restrict__ b_ih0, const float* __restrict__ b_hh0,
                       const float* __restrict__ W_ih1, const float* __restrict__ W_hh1,
                       const float* __restrict__ b_ih1, const float* __restrict__ b_hh1,
                       const float* __restrict__ W_fc,  const float* __restrict__ b_fc,
                       float* __restrict__ out)
{
    ull* w0 = smem + W0_ULL;
    ull* wc = smem + WC_ULL;

    const int tid = threadIdx.x;
    const int hp  = tid & 31;           // lane: owns h-channels {2hp, 2hp+1}
    const int wid = tid >> 5;
    const int gb0 = blockIdx.x * NB + wid * J;   // this warp's first global batch

    ull* h0w = smem + HB_ULL + wid * (2 * J * 32);   // warp-private h0 [J][32]
    ull* h1w = h0w + J * 32;                          // warp-private h1 [J][32]

    // ---- build k-pair-packed weight tiles ----
    for (int i = tid; i < 32 * 256; i += NTHREADS){
        int kp = i >> 8, row = i & 255;
        w0[i] = pack2(W_hh0[row * H + 2*kp], W_hh0[row * H + 2*kp + 1]);
    }
    for (int i = tid; i < 64 * 256; i += NTHREADS){
        int kp = i >> 8, row = i & 255;
        const float* Ws = (kp < 32) ? W_ih1 : W_hh1;
        int kk = (kp & 31) * 2;
        wc[i] = pack2(Ws[row * H + kk], Ws[row * H + kk + 1]);
    }
    for (int i = hp; i < 2 * J * 32; i += 32) h0w[i] = 0ull;

    // ---- per-lane constants: rows {g*64+2hp, g*64+2hp+1} ----
    float bias0[4][2], bias1[4][2], wih0r[4][2];
    #pragma unroll
    for (int g = 0; g < 4; g++){
        int ra = g * 64 + 2 * hp, rb = ra + 1;
        bias0[g][0] = b_ih0[ra] + b_hh0[ra];  bias0[g][1] = b_ih0[rb] + b_hh0[rb];
        bias1[g][0] = b_ih1[ra] + b_hh1[ra];  bias1[g][1] = b_ih1[rb] + b_hh1[rb];
        wih0r[g][0] = W_ih0[ra];              wih0r[g][1] = W_ih0[rb];
    }
    const float wfc0 = W_fc[2 * hp], wfc1 = W_fc[2 * hp + 1];

    float c0[J][2], c1[J][2];
    #pragma unroll
    for (int j = 0; j < J; j++){
        c0[j][0] = c0[j][1] = 0.0f;
        c1[j][0] = c1[j][1] = 0.0f;
    }

    __syncthreads();   // weights + h ready; from here on, warp-independent

    for (int t = 0; t < T_STEPS; t++){
        float xv[J];
        #pragma unroll
        for (int j = 0; j < J; j++)
            xv[j] = __ldg(&x[(gb0 + j) * T_STEPS + t]);

        // ======== layer 0 ========
        ull acc[J][4][2];
        #pragma unroll
        for (int j = 0; j < J; j++)
            #pragma unroll
            for (int g = 0; g < 4; g++){ acc[j][g][0] = 0ull; acc[j][g][1] = 0ull; }

        gemm64k(acc, w0, h0w, hp);

        ull hnew[J];
        #pragma unroll
        for (int j = 0; j < J; j++){
            float vi0 = sum2(acc[j][0][0]) + fmaf(xv[j], wih0r[0][0], bias0[0][0]);
            float vi1 = sum2(acc[j][0][1]) + fmaf(xv[j], wih0r[0][1], bias0[0][1]);
            float vf0 = sum2(acc[j][1][0]) + fmaf(xv[j], wih0r[1][0], bias0[1][0]);
            float vf1 = sum2(acc[j][1][1]) + fmaf(xv[j], wih0r[1][1], bias0[1][1]);
            float vg0 = sum2(acc[j][2][0]) + fmaf(xv[j], wih0r[2][0], bias0[2][0]);
            float vg1 = sum2(acc[j][2][1]) + fmaf(xv[j], wih0r[2][1], bias0[2][1]);
            float vo0 = sum2(acc[j][3][0]) + fmaf(xv[j], wih0r[3][0], bias0[3][0]);
            float vo1 = sum2(acc[j][3][1]) + fmaf(xv[j], wih0r[3][1], bias0[3][1]);
            float ccx = sigm(vf0) * c0[j][0] + sigm(vi0) * tanh_f(vg0);
            float ccy = sigm(vf1) * c0[j][1] + sigm(vi1) * tanh_f(vg1);
            c0[j][0] = ccx; c0[j][1] = ccy;
            hnew[j] = pack2(sigm(vo0) * tanh_f(ccx), sigm(vo1) * tanh_f(ccy));
        }
        __syncwarp();                       // all lanes done reading h0w
        #pragma unroll
        for (int j = 0; j < J; j++) h0w[j * 32 + hp] = hnew[j];
        __syncwarp();                       // h0[t] visible to all lanes

        // ======== layer 1 ========
        #pragma unroll
        for (int j = 0; j < J; j++)
            #pragma unroll
            for (int g = 0; g < 4; g++){ acc[j][g][0] = 0ull; acc[j][g][1] = 0ull; }

        gemm64k(acc, wc,            h0w, hp);   // W_ih1 * h0[t]
        gemm64k(acc, wc + 32 * 256, h1w, hp);   // W_hh1 * h1[t-1]

        #pragma unroll
        for (int j = 0; j < J; j++){
            float vi0 = sum2(acc[j][0][0]) + bias1[0][0];
            float vi1 = sum2(acc[j][0][1]) + bias1[0][1];
            float vf0 = sum2(acc[j][1][0]) + bias1[1][0];
            float vf1 = sum2(acc[j][1][1]) + bias1[1][1];
            float vg0 = sum2(acc[j][2][0]) + bias1[2][0];
            float vg1 = sum2(acc[j][2][1]) + bias1[2][1];
            float vo0 = sum2(acc[j][3][0]) + bias1[3][0];
            float vo1 = sum2(acc[j][3][1]) + bias1[3][1];
            float ccx = sigm(vf0) * c1[j][0] + sigm(vi0) * tanh_f(vg0);
            float ccy = sigm(vf1) * c1[j][1] + sigm(vi1) * tanh_f(vg1);
            c1[j][0] = ccx; c1[j][1] = ccy;
            hnew[j] = pack2(sigm(vo0) * tanh_f(ccx), sigm(vo1) * tanh_f(ccy));
        }
        __syncwarp();
        #pragma unroll
        for (int j = 0; j < J; j++) h1w[j * 32 + hp] = hnew[j];
        __syncwarp();
    }

    // ---- final FC: warp-reduce h1[T-1] . W_fc per owned batch ----
    #pragma unroll
    for (int j = 0; j < J; j++){
        float2 h2 = unpack2(h1w[j * 32 + hp]);
        float s = h2.x * wfc0 + h2.y * wfc1;
        #pragma unroll
        for (int off = 16; off > 0; off >>= 1)
            s += __shfl_xor_sync(0xFFFFFFFFu, s, off);
        if (hp == 0) out[gb0 + j] = s + b_fc[0];
    }
}

extern "C" void kernel_launch(void* const* d_in, const int* in_sizes, int n_in,
                              void* d_out, int out_size)
{
    const float* x     = (const float*)d_in[0];
    const float* W_ih0 = (const float*)d_in[1];
    const float* W_hh0 = (const float*)d_in[2];
    const float* b_ih0 = (const float*)d_in[3];
    const float* b_hh0 = (const float*)d_in[4];
    const float* W_ih1 = (const float*)d_in[5];
    const float* W_hh1 = (const float*)d_in[6];
    const float* b_ih1 = (const float*)d_in[7];
    const float* b_hh1 = (const float*)d_in[8];
    const float* W_fc  = (const float*)d_in[9];
    const float* b_fc  = (const float*)d_in[10];
    float* out = (float*)d_out;

    cudaFuncSetAttribute(lstm_forecaster_kernel,
                         cudaFuncAttributeMaxDynamicSharedMemorySize, SMEM_BYTES);
    lstm_forecaster_kernel<<<B_TOTAL / NB, NTHREADS, SMEM_BYTES>>>(
        x, W_ih0, W_hh0, b_ih0, b_hh0,
        W_ih1, W_hh1, b_ih1, b_hh1, W_fc, b_fc, out);
}